// round 1
// baseline (speedup 1.0000x reference)
#include <cuda_runtime.h>
#include <math_constants.h>

// Problem constants (fixed shapes from reference setup_inputs)
#define Bv      32
#define Kv      17
#define Ww      128
#define HW      16384          // 128*128
#define CPAF    38
#define Ev      19
#define KK      8
#define NB_HEAT (Bv * Kv)      // 544 blocks, one per (b,k)
#define NB_PAF  1184           // grid-stride partial blocks for PAF
#define THREADS 256

// Scratch (no cudaMalloc allowed) — fully overwritten every launch.
__device__ float g_kpSum[NB_HEAT];      // sum of squared diffs per (b,k)
__device__ int   g_kpArg[NB_HEAT];      // argmax index (first occurrence) per (b,k)
__device__ float g_pafPartial[NB_PAF];  // per-block PAF partial sums

// COCO_PERSON_SKELETON edges
__constant__ int c_eA[Ev] = {15,13,16,14,11, 5, 6, 5, 5, 6, 7, 8, 1, 0, 0, 1, 2, 3, 4};
__constant__ int c_eB[Ev] = {13,11,14,12,12,11,12, 6, 7, 8, 9,10, 2, 1, 2, 3, 4, 5, 6};

// ---------------------------------------------------------------------------
// Kernel 1 (fused): blocks [0, 544)  -> per-(b,k) heatmap sumsq + argmax
//                   blocks [544, ..) -> PAF sum-of-squared-diff partials
// ---------------------------------------------------------------------------
__global__ void __launch_bounds__(THREADS)
pose_reduce_kernel(const float* __restrict__ hp, const float* __restrict__ hg,
                   const float* __restrict__ pp, const float* __restrict__ pg)
{
    const int t = threadIdx.x;

    if (blockIdx.x < NB_HEAT) {
        // ---- heatmap path: 16384 elems = 4096 float4 per block ----
        const int bk = blockIdx.x;
        const float4* a4 = reinterpret_cast<const float4*>(hp + (size_t)bk * HW);
        const float4* b4 = reinterpret_cast<const float4*>(hg + (size_t)bk * HW);

        float sum = 0.0f;
        float mx  = -CUDART_INF_F;
        int   mi  = 0;

        #pragma unroll 4
        for (int i = t; i < HW / 4; i += THREADS) {
            float4 a = __ldg(a4 + i);
            float4 b = __ldg(b4 + i);
            float d0 = a.x - b.x, d1 = a.y - b.y, d2 = a.z - b.z, d3 = a.w - b.w;
            sum += d0 * d0 + d1 * d1 + d2 * d2 + d3 * d3;
            const int base = i << 2;
            // indices strictly increase per thread -> strict '>' keeps first occurrence
            if (a.x > mx) { mx = a.x; mi = base;     }
            if (a.y > mx) { mx = a.y; mi = base + 1; }
            if (a.z > mx) { mx = a.z; mi = base + 2; }
            if (a.w > mx) { mx = a.w; mi = base + 3; }
        }

        // warp reduction (sum + argmax with min-index tiebreak)
        #pragma unroll
        for (int o = 16; o; o >>= 1) {
            float os = __shfl_down_sync(0xffffffffu, sum, o);
            float om = __shfl_down_sync(0xffffffffu, mx,  o);
            int   oi = __shfl_down_sync(0xffffffffu, mi,  o);
            sum += os;
            if (om > mx || (om == mx && oi < mi)) { mx = om; mi = oi; }
        }

        __shared__ float s_sum[8];
        __shared__ float s_mx[8];
        __shared__ int   s_mi[8];
        const int w = t >> 5;
        if ((t & 31) == 0) { s_sum[w] = sum; s_mx[w] = mx; s_mi[w] = mi; }
        __syncthreads();
        if (t == 0) {
            #pragma unroll
            for (int i = 1; i < 8; i++) {
                sum += s_sum[i];
                if (s_mx[i] > mx || (s_mx[i] == mx && s_mi[i] < mi)) {
                    mx = s_mx[i]; mi = s_mi[i];
                }
            }
            g_kpSum[bk] = sum;
            g_kpArg[bk] = mi;
        }
    } else {
        // ---- PAF path: grid-stride over 4,980,736 float4 ----
        const int pb = blockIdx.x - NB_HEAT;
        const float4* a4 = reinterpret_cast<const float4*>(pp);
        const float4* b4 = reinterpret_cast<const float4*>(pg);
        const int n4 = (Bv * CPAF * HW) / 4;

        float sum = 0.0f;
        for (int i = pb * THREADS + t; i < n4; i += NB_PAF * THREADS) {
            float4 a = __ldg(a4 + i);
            float4 b = __ldg(b4 + i);
            float d0 = a.x - b.x, d1 = a.y - b.y, d2 = a.z - b.z, d3 = a.w - b.w;
            sum += d0 * d0 + d1 * d1 + d2 * d2 + d3 * d3;
        }

        #pragma unroll
        for (int o = 16; o; o >>= 1)
            sum += __shfl_down_sync(0xffffffffu, sum, o);

        __shared__ float s[8];
        const int w = t >> 5;
        if ((t & 31) == 0) s[w] = sum;
        __syncthreads();
        if (t == 0) {
            float tot = 0.0f;
            #pragma unroll
            for (int i = 0; i < 8; i++) tot += s[i];
            g_pafPartial[pb] = tot;
        }
    }
}

// ---------------------------------------------------------------------------
// Kernel 2: finalize — PAF partial reduce, per-batch top-8 OHKM, struct loss
// ---------------------------------------------------------------------------
__global__ void __launch_bounds__(THREADS)
pose_finalize_kernel(const int* __restrict__ coords, float* __restrict__ out,
                     int out_size)
{
    __shared__ float s_paf[THREADS];
    __shared__ float s_batch[Bv];
    const int t = threadIdx.x;

    // reduce PAF partials (fixed-order, deterministic)
    float p = 0.0f;
    for (int i = t; i < NB_PAF; i += THREADS) p += g_pafPartial[i];
    s_paf[t] = p;
    __syncthreads();
    #pragma unroll
    for (int s = THREADS / 2; s; s >>= 1) {
        if (t < s) s_paf[t] += s_paf[t + s];
        __syncthreads();
    }

    if (t < Bv) {
        // ---- OHKM: top-8-of-17 per-kp mean MSE ----
        float v[Kv];
        #pragma unroll
        for (int k = 0; k < Kv; k++) v[k] = g_kpSum[t * Kv + k] * (1.0f / HW);

        float tsum = 0.0f;
        #pragma unroll
        for (int j = 0; j < KK; j++) {
            float mv = v[0]; int mk = 0;
            #pragma unroll
            for (int k = 1; k < Kv; k++)
                if (v[k] > mv) { mv = v[k]; mk = k; }
            tsum += mv;
            v[mk] = -CUDART_INF_F;
        }
        const float heat = tsum * (1.0f / KK);

        // ---- struct loss ----
        float px[Kv], py[Kv], gx[Kv], gy[Kv];
        #pragma unroll
        for (int k = 0; k < Kv; k++) {
            const int idx = g_kpArg[t * Kv + k];
            px[k] = (float)(idx & (Ww - 1));
            py[k] = (float)(idx >> 7);
            gx[k] = (float)coords[(t * Kv + k) * 2 + 0];
            gy[k] = (float)coords[(t * Kv + k) * 2 + 1];
        }
        float ss = 0.0f;
        #pragma unroll
        for (int e = 0; e < Ev; e++) {
            const int a = c_eA[e], b = c_eB[e];
            const float dx = px[a] - px[b], dy = py[a] - py[b];
            const float pl = sqrtf(dx * dx + dy * dy);
            const float hx = gx[a] - gx[b], hy = gy[a] - gy[b];
            const float gl = sqrtf(hx * hx + hy * hy);
            const float d = pl - gl;
            ss += d * d;
        }
        s_batch[t] = heat + ss / ((float)Ev + 1e-6f);
    }
    __syncthreads();

    if (t == 0) {
        float acc = 0.0f;
        #pragma unroll
        for (int b = 0; b < Bv; b++) acc += s_batch[b];
        const float total = acc * (1.0f / Bv)
                          + s_paf[0] / ((float)Bv * CPAF * HW);
        for (int i = 0; i < out_size; i++) out[i] = total;
    }
}

// ---------------------------------------------------------------------------
extern "C" void kernel_launch(void* const* d_in, const int* in_sizes, int n_in,
                              void* d_out, int out_size)
{
    const float* hp     = (const float*)d_in[0];  // heatmap_pred (32,17,128,128)
    const float* pp     = (const float*)d_in[1];  // paf_pred     (32,38,128,128)
    const float* hg     = (const float*)d_in[2];  // heatmap_gt
    const float* pg     = (const float*)d_in[3];  // paf_gt
    const int*   coords = (const int*)d_in[4];    // joint_coords_gt (32,17,2)

    pose_reduce_kernel<<<NB_HEAT + NB_PAF, THREADS>>>(hp, hg, pp, pg);
    pose_finalize_kernel<<<1, THREADS>>>(coords, (float*)d_out, out_size);
}